// round 6
// baseline (speedup 1.0000x reference)
#include <cuda_runtime.h>
#include <cuda_bf16.h>

// Shapes: anchors (N=1024,2) f32; gt_boxes (B=128, M=256, 4) f32.
// Output f32: [matches (B*M) | ious (B,N,M)].
#define N_ANCH 1024
#define B_     128
#define M_     256

#define M_PER_CTA 16
#define NQ        4                  // m-quads per CTA (16/4)
#define NCH       64                 // anchor chunks per CTA
#define CH        (N_ANCH / NCH)     // 16 anchors per chunk
#define NTHREADS  (NQ * NCH)         // 256

typedef unsigned long long u64;

// ---- packed f32x2 helpers (sm_103a; PTX-only) ----
__device__ __forceinline__ u64 pk(float lo, float hi) {
    u64 d; asm("mov.b64 %0, {%1, %2};" : "=l"(d) : "f"(lo), "f"(hi)); return d;
}
__device__ __forceinline__ void upk(u64 v, float& lo, float& hi) {
    asm("mov.b64 {%0, %1}, %2;" : "=f"(lo), "=f"(hi) : "l"(v));
}
__device__ __forceinline__ u64 mul2(u64 a, u64 b) {
    u64 d; asm("mul.rn.f32x2 %0, %1, %2;" : "=l"(d) : "l"(a), "l"(b)); return d;
}
__device__ __forceinline__ u64 add2(u64 a, u64 b) {
    u64 d; asm("add.rn.f32x2 %0, %1, %2;" : "=l"(d) : "l"(a), "l"(b)); return d;
}
__device__ __forceinline__ u64 fma2(u64 a, u64 b, u64 c) {
    u64 d; asm("fma.rn.f32x2 %0, %1, %2, %3;" : "=l"(d) : "l"(a), "l"(b), "l"(c)); return d;
}
__device__ __forceinline__ float rcpa(float x) {
    float r; asm("rcp.approx.f32 %0, %1;" : "=f"(r) : "f"(x)); return r;
}

// Packed correctly-rounded q = x / (s - x): exact ptxas div.rn fast path
// (rcp + Newton + residual fixup). Operands always normal / well-scaled
// (x in [2.5e-3,1], s-x in [2.5e-3,2]) so the slow path can't trip:
// bit-identical to IEEE div.rn -> rel_err stays 0, argmax exact.
__device__ __forceinline__ u64 iou_div2(u64 x, u64 s) {
    const u64 NEG1 = 0xBF800000BF800000ULL;
    const u64 ONE  = 0x3F8000003F800000ULL;
    u64 y  = fma2(x, NEG1, s);                // uni = s - x
    u64 ny = mul2(y, NEG1);                   // -uni (exact)
    float y0, y1; upk(y, y0, y1);
    u64 r  = pk(rcpa(y0), rcpa(y1));
    u64 e  = fma2(ny, r, ONE);
    r      = fma2(r, e, r);
    u64 q  = mul2(x, r);
    u64 rem = fma2(ny, q, x);
    return fma2(rem, r, q);
}

// Grid (B, M/16) = 2048 CTAs, block 256, forced 6 CTAs/SM.
//   mq = tid & 3  -> m = mbase + 4*mq .. +3 (one 16B store per anchor)
//   ch = tid >> 2 -> anchors [ch*16, ch*16+16)
__global__ void __launch_bounds__(NTHREADS, 6)
matcher_kernel(const float* __restrict__ anchors,
               const float* __restrict__ gt,
               float* __restrict__ matches,
               float* __restrict__ ious)
{
    __shared__ float2 sWH[N_ANCH];           // {aw, ah}           8 KB
    __shared__ u64    sAZ[N_ANCH];           // {area, area} pair  8 KB
    __shared__ float  sPm[NCH][M_PER_CTA];   // per-chunk best iou 4 KB
    __shared__ int    sPi[NCH][M_PER_CTA];   // per-chunk best n   4 KB

    const int tid = threadIdx.x;
    const int mq  = tid & (NQ - 1);
    const int ch  = tid >> 2;
    const int b     = blockIdx.x;
    const int mbase = blockIdx.y * M_PER_CTA;
    const int m0    = mbase + 4 * mq;

    // Stage anchors once: widths/heights + pre-packed {area,area}.
    // Centered boxes => iw = min(aw,gw) bitwise (0.5w exact; clips dead).
    for (int i = tid; i < N_ANCH; i += NTHREADS) {
        const float2 a = reinterpret_cast<const float2*>(anchors)[i];
        sWH[i] = a;
        const float az = a.x * a.y;
        sAZ[i] = pk(az, az);
    }
    __syncthreads();

    float gw[4], gh[4], aB[4];
    #pragma unroll
    for (int j = 0; j < 4; j++) {
        const float4 g = reinterpret_cast<const float4*>(gt)[b * M_ + m0 + j];
        gw[j] = g.z - g.x;
        gh[j] = g.w - g.y;
        aB[j] = gw[j] * gh[j];
    }
    const u64 aB01 = pk(aB[0], aB[1]);
    const u64 aB23 = pk(aB[2], aB[3]);

    float best[4]  = {-1.0f, -1.0f, -1.0f, -1.0f};
    int   bestn[4] = {0, 0, 0, 0};

    ulonglong2* pp = reinterpret_cast<ulonglong2*>(
        ious + (size_t)b * N_ANCH * M_ + (size_t)ch * CH * M_ + m0);

    #pragma unroll 4
    for (int i = 0; i < CH; i++) {
        const float2 a  = sWH[ch * CH + i];
        const u64    az = sAZ[ch * CH + i];
        const u64 iw01 = pk(fminf(a.x, gw[0]), fminf(a.x, gw[1]));
        const u64 ih01 = pk(fminf(a.y, gh[0]), fminf(a.y, gh[1]));
        const u64 iw23 = pk(fminf(a.x, gw[2]), fminf(a.x, gw[3]));
        const u64 ih23 = pk(fminf(a.y, gh[2]), fminf(a.y, gh[3]));
        const u64 x01  = mul2(iw01, ih01);          // inter
        const u64 x23  = mul2(iw23, ih23);
        const u64 s01  = add2(az, aB01);            // area_a + area_b
        const u64 s23  = add2(az, aB23);
        const u64 q01  = iou_div2(x01, s01);
        const u64 q23  = iou_div2(x23, s23);

        ulonglong2 st; st.x = q01; st.y = q23;
        *pp = st;
        pp += M_ / 4;

        float r0, r1, r2, r3;
        upk(q01, r0, r1); upk(q23, r2, r3);
        if (r0 > best[0]) { best[0] = r0; bestn[0] = i; }
        if (r1 > best[1]) { best[1] = r1; bestn[1] = i; }
        if (r2 > best[2]) { best[2] = r2; bestn[2] = i; }
        if (r3 > best[3]) { best[3] = r3; bestn[3] = i; }
    }

    #pragma unroll
    for (int j = 0; j < 4; j++) {
        sPm[ch][4 * mq + j] = best[j];
        sPi[ch][4 * mq + j] = ch * CH + bestn[j];
    }
    __syncthreads();

    // Fold chunks ascending, strict-greater: first-occurring max wins,
    // matching jnp.argmax exactly.
    if (tid < M_PER_CTA) {
        float bv = sPm[0][tid];
        int   bi = sPi[0][tid];
        #pragma unroll
        for (int c = 1; c < NCH; c++) {
            const float v = sPm[c][tid];
            if (v > bv) { bv = v; bi = sPi[c][tid]; }
        }
        matches[b * M_ + mbase + tid] = (float)bi;
    }
}

extern "C" void kernel_launch(void* const* d_in, const int* in_sizes, int n_in,
                              void* d_out, int out_size)
{
    const float* anchors = (const float*)d_in[0];
    const float* gt      = (const float*)d_in[1];
    float* out = (float*)d_out;

    const size_t ious_elems = (size_t)B_ * N_ANCH * M_;
    const size_t ious_off   = (size_t)out_size - ious_elems;

    matcher_kernel<<<dim3(B_, M_ / M_PER_CTA), NTHREADS>>>(
        anchors, gt, out, out + ious_off);
}

// round 7
// speedup vs baseline: 1.1463x; 1.1463x over previous
#include <cuda_runtime.h>
#include <cuda_bf16.h>

// Shapes: anchors (N=1024,2) f32; gt_boxes (B=128, M=256, 4) f32.
// Output f32: [matches (B*M) | ious (B,N,M)].
#define N_ANCH 1024
#define B_     128
#define M_     256

#define M_PER_CTA 32
#define NQ        8                  // m-quads per CTA (32/4): warp covers 128B/row
#define NCH       32                 // anchor chunks per CTA
#define CH        (N_ANCH / NCH)     // 32 anchors per chunk
#define NTHREADS  (NQ * NCH)         // 256

typedef unsigned long long u64;

// ---- packed f32x2 helpers (sm_103a; PTX-only) ----
__device__ __forceinline__ u64 pk(float lo, float hi) {
    u64 d; asm("mov.b64 %0, {%1, %2};" : "=l"(d) : "f"(lo), "f"(hi)); return d;
}
__device__ __forceinline__ void upk(u64 v, float& lo, float& hi) {
    asm("mov.b64 {%0, %1}, %2;" : "=f"(lo), "=f"(hi) : "l"(v));
}
__device__ __forceinline__ u64 mul2(u64 a, u64 b) {
    u64 d; asm("mul.rn.f32x2 %0, %1, %2;" : "=l"(d) : "l"(a), "l"(b)); return d;
}
__device__ __forceinline__ u64 add2(u64 a, u64 b) {
    u64 d; asm("add.rn.f32x2 %0, %1, %2;" : "=l"(d) : "l"(a), "l"(b)); return d;
}
__device__ __forceinline__ u64 fma2(u64 a, u64 b, u64 c) {
    u64 d; asm("fma.rn.f32x2 %0, %1, %2, %3;" : "=l"(d) : "l"(a), "l"(b), "l"(c)); return d;
}
__device__ __forceinline__ float rcpa(float x) {
    float r; asm("rcp.approx.f32 %0, %1;" : "=f"(r) : "f"(x)); return r;
}

// Packed correctly-rounded q = x / (s - x): exact ptxas div.rn fast path
// (rcp + Newton + residual fixup). Operands always normal / well-scaled
// (x in [2.5e-3,1], s-x in [2.5e-3,2]) so the slow path can't trip:
// bit-identical to IEEE div.rn -> rel_err stays 0, argmax exact.
__device__ __forceinline__ u64 iou_div2(u64 x, u64 s) {
    const u64 NEG1 = 0xBF800000BF800000ULL;
    const u64 ONE  = 0x3F8000003F800000ULL;
    u64 y  = fma2(x, NEG1, s);                // uni = s - x
    u64 ny = mul2(y, NEG1);                   // -uni (exact)
    float y0, y1; upk(y, y0, y1);
    u64 r  = pk(rcpa(y0), rcpa(y1));
    u64 e  = fma2(ny, r, ONE);
    r      = fma2(r, e, r);
    u64 q  = mul2(x, r);
    u64 rem = fma2(ny, q, x);
    return fma2(rem, r, q);
}

// Grid (B, M/32) = 1024 CTAs, block 256, forced 6 CTAs/SM (regs <= 42; the
// identical body compiled to 40 in R5).
//   mq = tid & 7  -> m = mbase + 4*mq .. +3 (one 16B store per anchor)
//   ch = tid >> 3 -> anchors [ch*32, ch*32+32)
__global__ void __launch_bounds__(NTHREADS, 6)
matcher_kernel(const float* __restrict__ anchors,
               const float* __restrict__ gt,
               float* __restrict__ matches,
               float* __restrict__ ious)
{
    __shared__ float2 sWH[N_ANCH];           // {aw, ah}           8 KB
    __shared__ u64    sAZ[N_ANCH];           // {area, area} pair  8 KB
    __shared__ float  sPm[NCH][M_PER_CTA];   // per-chunk best iou 4 KB
    __shared__ int    sPi[NCH][M_PER_CTA];   // per-chunk best n   4 KB

    const int tid = threadIdx.x;
    const int mq  = tid & (NQ - 1);
    const int ch  = tid >> 3;
    const int b     = blockIdx.x;
    const int mbase = blockIdx.y * M_PER_CTA;
    const int m0    = mbase + 4 * mq;

    // Stage anchors once: widths/heights + pre-packed {area,area}.
    // Centered boxes => iw = min(aw,gw) bitwise (0.5w exact; clips dead).
    for (int i = tid; i < N_ANCH; i += NTHREADS) {
        const float2 a = reinterpret_cast<const float2*>(anchors)[i];
        sWH[i] = a;
        const float az = a.x * a.y;
        sAZ[i] = pk(az, az);
    }
    __syncthreads();

    float gw[4], gh[4], aB[4];
    #pragma unroll
    for (int j = 0; j < 4; j++) {
        const float4 g = reinterpret_cast<const float4*>(gt)[b * M_ + m0 + j];
        gw[j] = g.z - g.x;
        gh[j] = g.w - g.y;
        aB[j] = gw[j] * gh[j];
    }
    const u64 aB01 = pk(aB[0], aB[1]);
    const u64 aB23 = pk(aB[2], aB[3]);

    float best[4]  = {-1.0f, -1.0f, -1.0f, -1.0f};
    int   bestn[4] = {0, 0, 0, 0};

    ulonglong2* pp = reinterpret_cast<ulonglong2*>(
        ious + (size_t)b * N_ANCH * M_ + (size_t)ch * CH * M_ + m0);

    #pragma unroll 8
    for (int i = 0; i < CH; i++) {
        const float2 a  = sWH[ch * CH + i];
        const u64    az = sAZ[ch * CH + i];
        const u64 iw01 = pk(fminf(a.x, gw[0]), fminf(a.x, gw[1]));
        const u64 ih01 = pk(fminf(a.y, gh[0]), fminf(a.y, gh[1]));
        const u64 iw23 = pk(fminf(a.x, gw[2]), fminf(a.x, gw[3]));
        const u64 ih23 = pk(fminf(a.y, gh[2]), fminf(a.y, gh[3]));
        const u64 x01  = mul2(iw01, ih01);          // inter
        const u64 x23  = mul2(iw23, ih23);
        const u64 s01  = add2(az, aB01);            // area_a + area_b
        const u64 s23  = add2(az, aB23);
        const u64 q01  = iou_div2(x01, s01);
        const u64 q23  = iou_div2(x23, s23);

        ulonglong2 st; st.x = q01; st.y = q23;
        *pp = st;
        pp += M_ / 4;

        float r0, r1, r2, r3;
        upk(q01, r0, r1); upk(q23, r2, r3);
        if (r0 > best[0]) { best[0] = r0; bestn[0] = i; }
        if (r1 > best[1]) { best[1] = r1; bestn[1] = i; }
        if (r2 > best[2]) { best[2] = r2; bestn[2] = i; }
        if (r3 > best[3]) { best[3] = r3; bestn[3] = i; }
    }

    #pragma unroll
    for (int j = 0; j < 4; j++) {
        sPm[ch][4 * mq + j] = best[j];
        sPi[ch][4 * mq + j] = ch * CH + bestn[j];
    }
    __syncthreads();

    // Fold chunks ascending, strict-greater: first-occurring max wins,
    // matching jnp.argmax exactly.
    if (tid < M_PER_CTA) {
        float bv = sPm[0][tid];
        int   bi = sPi[0][tid];
        #pragma unroll
        for (int c = 1; c < NCH; c++) {
            const float v = sPm[c][tid];
            if (v > bv) { bv = v; bi = sPi[c][tid]; }
        }
        matches[b * M_ + mbase + tid] = (float)bi;
    }
}

extern "C" void kernel_launch(void* const* d_in, const int* in_sizes, int n_in,
                              void* d_out, int out_size)
{
    const float* anchors = (const float*)d_in[0];
    const float* gt      = (const float*)d_in[1];
    float* out = (float*)d_out;

    const size_t ious_elems = (size_t)B_ * N_ANCH * M_;
    const size_t ious_off   = (size_t)out_size - ious_elems;

    matcher_kernel<<<dim3(B_, M_ / M_PER_CTA), NTHREADS>>>(
        anchors, gt, out, out + ious_off);
}

// round 8
// speedup vs baseline: 1.3558x; 1.1827x over previous
#include <cuda_runtime.h>
#include <cuda_bf16.h>

// Shapes: anchors (N=1024,2) f32; gt_boxes (B=128, M=256, 4) f32.
// Output f32: [matches (B*M) | ious (B,N,M)].
#define N_ANCH 1024
#define B_     128
#define M_     256

#define M_PER_CTA 32
#define NQ        8                  // m-quads per CTA: warp covers 128B/row
#define NCH       32                 // anchor chunks per CTA
#define CH        (N_ANCH / NCH)     // 32 anchors per chunk
#define NTHREADS  (NQ * NCH)         // 256

typedef unsigned long long u64;

// ---- packed f32x2 helpers (sm_103a; PTX-only) ----
__device__ __forceinline__ u64 pk(float lo, float hi) {
    u64 d; asm("mov.b64 %0, {%1, %2};" : "=l"(d) : "f"(lo), "f"(hi)); return d;
}
__device__ __forceinline__ void upk(u64 v, float& lo, float& hi) {
    asm("mov.b64 {%0, %1}, %2;" : "=f"(lo), "=f"(hi) : "l"(v));
}
__device__ __forceinline__ u64 mul2(u64 a, u64 b) {
    u64 d; asm("mul.rn.f32x2 %0, %1, %2;" : "=l"(d) : "l"(a), "l"(b)); return d;
}
__device__ __forceinline__ u64 add2(u64 a, u64 b) {
    u64 d; asm("add.rn.f32x2 %0, %1, %2;" : "=l"(d) : "l"(a), "l"(b)); return d;
}
__device__ __forceinline__ u64 fma2(u64 a, u64 b, u64 c) {
    u64 d; asm("fma.rn.f32x2 %0, %1, %2, %3;" : "=l"(d) : "l"(a), "l"(b), "l"(c)); return d;
}
__device__ __forceinline__ float rcpa(float x) {
    float r; asm("rcp.approx.f32 %0, %1;" : "=f"(r) : "f"(x)); return r;
}

// Packed correctly-rounded q = x / (s - x): exact ptxas div.rn fast path
// (rcp + Newton + residual fixup). Operands always normal / well-scaled
// (x in [2.5e-3,1], s-x in [2.5e-3,2]) so the slow path can't trip:
// bit-identical to IEEE div.rn -> rel_err stays 0, argmax exact.
__device__ __forceinline__ u64 iou_div2(u64 x, u64 s) {
    const u64 NEG1 = 0xBF800000BF800000ULL;
    const u64 ONE  = 0x3F8000003F800000ULL;
    u64 y  = fma2(x, NEG1, s);                // uni = s - x
    u64 ny = mul2(y, NEG1);                   // -uni (exact)
    float y0, y1; upk(y, y0, y1);
    u64 r  = pk(rcpa(y0), rcpa(y1));
    u64 e  = fma2(ny, r, ONE);
    r      = fma2(r, e, r);
    u64 q  = mul2(x, r);
    u64 rem = fma2(ny, q, x);
    return fma2(rem, r, q);
}

// Grid (B, M/32) = 1024 CTAs, block 256, 6 CTAs/SM. Unroll 4 (the unroll-8
// body spilled under the 40-reg cap in R6 -- L1 74% signature; unroll-4 fits).
//   mq = tid & 7  -> m = mbase + 4*mq .. +3 (one 16B store per anchor)
//   ch = tid >> 3 -> anchors [ch*32, ch*32+32)
__global__ void __launch_bounds__(NTHREADS, 6)
matcher_kernel(const float* __restrict__ anchors,
               const float* __restrict__ gt,
               float* __restrict__ matches,
               float* __restrict__ ious)
{
    __shared__ float4 sA[N_ANCH];            // {aw, ah, az, az}  16 KB
    __shared__ float  sPm[NCH][M_PER_CTA];   // per-chunk best iou 4 KB
    __shared__ int    sPi[NCH][M_PER_CTA];   // per-chunk best n   4 KB

    const int tid = threadIdx.x;
    const int mq  = tid & (NQ - 1);
    const int ch  = tid >> 3;
    const int b     = blockIdx.x;
    const int mbase = blockIdx.y * M_PER_CTA;
    const int m0    = mbase + 4 * mq;

    // Stage anchors once. {az,az} lives in the z/w pair so the packed area
    // u64 is materialized straight from the LDS.128 register pair.
    // Centered boxes => iw = min(aw,gw) bitwise (0.5w exact; clips dead).
    for (int i = tid; i < N_ANCH; i += NTHREADS) {
        const float2 a = reinterpret_cast<const float2*>(anchors)[i];
        const float az = a.x * a.y;
        sA[i] = make_float4(a.x, a.y, az, az);
    }
    __syncthreads();

    float gw[4], gh[4], aB[4];
    #pragma unroll
    for (int j = 0; j < 4; j++) {
        const float4 g = reinterpret_cast<const float4*>(gt)[b * M_ + m0 + j];
        gw[j] = g.z - g.x;
        gh[j] = g.w - g.y;
        aB[j] = gw[j] * gh[j];
    }
    const u64 aB01 = pk(aB[0], aB[1]);
    const u64 aB23 = pk(aB[2], aB[3]);

    float best[4]  = {-1.0f, -1.0f, -1.0f, -1.0f};
    int   bestn[4] = {0, 0, 0, 0};

    float4* pp = reinterpret_cast<float4*>(
        ious + (size_t)b * N_ANCH * M_ + (size_t)ch * CH * M_ + m0);

    #pragma unroll 4
    for (int i = 0; i < CH; i++) {
        const float4 a  = sA[ch * CH + i];
        const u64    az = pk(a.z, a.w);             // register-pair alias
        const u64 iw01 = pk(fminf(a.x, gw[0]), fminf(a.x, gw[1]));
        const u64 ih01 = pk(fminf(a.y, gh[0]), fminf(a.y, gh[1]));
        const u64 iw23 = pk(fminf(a.x, gw[2]), fminf(a.x, gw[3]));
        const u64 ih23 = pk(fminf(a.y, gh[2]), fminf(a.y, gh[3]));
        const u64 x01  = mul2(iw01, ih01);          // inter
        const u64 x23  = mul2(iw23, ih23);
        const u64 s01  = add2(az, aB01);            // area_a + area_b
        const u64 s23  = add2(az, aB23);
        const u64 q01  = iou_div2(x01, s01);
        const u64 q23  = iou_div2(x23, s23);

        float r0, r1, r2, r3;
        upk(q01, r0, r1); upk(q23, r2, r3);

        // Streaming store: write-once data, evict-first in L2.
        __stcs(pp, make_float4(r0, r1, r2, r3));
        pp += M_ / 4;

        if (r0 > best[0]) { best[0] = r0; bestn[0] = i; }
        if (r1 > best[1]) { best[1] = r1; bestn[1] = i; }
        if (r2 > best[2]) { best[2] = r2; bestn[2] = i; }
        if (r3 > best[3]) { best[3] = r3; bestn[3] = i; }
    }

    #pragma unroll
    for (int j = 0; j < 4; j++) {
        sPm[ch][4 * mq + j] = best[j];
        sPi[ch][4 * mq + j] = ch * CH + bestn[j];
    }
    __syncthreads();

    // Fold chunks ascending, strict-greater: first-occurring max wins,
    // matching jnp.argmax exactly.
    if (tid < M_PER_CTA) {
        float bv = sPm[0][tid];
        int   bi = sPi[0][tid];
        #pragma unroll
        for (int c = 1; c < NCH; c++) {
            const float v = sPm[c][tid];
            if (v > bv) { bv = v; bi = sPi[c][tid]; }
        }
        matches[b * M_ + mbase + tid] = (float)bi;
    }
}

extern "C" void kernel_launch(void* const* d_in, const int* in_sizes, int n_in,
                              void* d_out, int out_size)
{
    const float* anchors = (const float*)d_in[0];
    const float* gt      = (const float*)d_in[1];
    float* out = (float*)d_out;

    const size_t ious_elems = (size_t)B_ * N_ANCH * M_;
    const size_t ious_off   = (size_t)out_size - ious_elems;

    matcher_kernel<<<dim3(B_, M_ / M_PER_CTA), NTHREADS>>>(
        anchors, gt, out, out + ious_off);
}

// round 9
// speedup vs baseline: 1.4329x; 1.0569x over previous
#include <cuda_runtime.h>
#include <cuda_bf16.h>

// Shapes: anchors (N=1024,2) f32; gt_boxes (B=128, M=256, 4) f32.
// Output f32: [matches (B*M) | ious (B,N,M)].
#define N_ANCH 1024
#define B_     128
#define M_     256

#define M_PER_CTA 32
#define NQ        8                  // m-quads per CTA: warp covers 128B/row
#define NCH       32                 // anchor chunks per CTA
#define CH        (N_ANCH / NCH)     // 32 anchors per chunk
#define NTHREADS  (NQ * NCH)         // 256

typedef unsigned long long u64;

// ---- packed f32x2 helpers (sm_103a; PTX-only) ----
__device__ __forceinline__ u64 pk(float lo, float hi) {
    u64 d; asm("mov.b64 %0, {%1, %2};" : "=l"(d) : "f"(lo), "f"(hi)); return d;
}
__device__ __forceinline__ void upk(u64 v, float& lo, float& hi) {
    asm("mov.b64 {%0, %1}, %2;" : "=f"(lo), "=f"(hi) : "l"(v));
}
__device__ __forceinline__ u64 mul2(u64 a, u64 b) {
    u64 d; asm("mul.rn.f32x2 %0, %1, %2;" : "=l"(d) : "l"(a), "l"(b)); return d;
}
__device__ __forceinline__ u64 add2(u64 a, u64 b) {
    u64 d; asm("add.rn.f32x2 %0, %1, %2;" : "=l"(d) : "l"(a), "l"(b)); return d;
}
__device__ __forceinline__ u64 fma2(u64 a, u64 b, u64 c) {
    u64 d; asm("fma.rn.f32x2 %0, %1, %2, %3;" : "=l"(d) : "l"(a), "l"(b), "l"(c)); return d;
}
__device__ __forceinline__ float rcpa(float x) {
    float r; asm("rcp.approx.f32 %0, %1;" : "=f"(r) : "f"(x)); return r;
}

// Packed correctly-rounded q = x / (s - x): exact ptxas div.rn fast path
// (rcp + Newton + residual fixup). Operands always normal / well-scaled
// (x in [2.5e-3,1], s-x in [2.5e-3,2]) so the slow path can't trip:
// bit-identical to IEEE div.rn -> rel_err stays 0, argmax exact.
__device__ __forceinline__ u64 iou_div2(u64 x, u64 s) {
    const u64 NEG1 = 0xBF800000BF800000ULL;
    const u64 ONE  = 0x3F8000003F800000ULL;
    u64 y  = fma2(x, NEG1, s);                // uni = s - x
    u64 ny = mul2(y, NEG1);                   // -uni (exact)
    float y0, y1; upk(y, y0, y1);
    u64 r  = pk(rcpa(y0), rcpa(y1));
    u64 e  = fma2(ny, r, ONE);
    r      = fma2(r, e, r);
    u64 q  = mul2(x, r);
    u64 rem = fma2(ny, q, x);
    return fma2(rem, r, q);
}

// R4 configuration (the proven local optimum): grid (B, M/32) = 1024 CTAs,
// block 256, NO launch_bounds cap (48 regs / 5 CTAs/SM natural), unroll 4.
//   mq = tid & 7  -> m = mbase + 4*mq .. +3 (one 16B store per anchor)
//   ch = tid >> 3 -> anchors [ch*32, ch*32+32)
__global__ void __launch_bounds__(NTHREADS)
matcher_kernel(const float* __restrict__ anchors,
               const float* __restrict__ gt,
               float* __restrict__ matches,
               float* __restrict__ ious)
{
    __shared__ float2 sWH[N_ANCH];           // {aw, ah}           8 KB
    __shared__ float  sPm[NCH][M_PER_CTA];   // per-chunk best iou 4 KB
    __shared__ int    sPi[NCH][M_PER_CTA];   // per-chunk best n   4 KB

    const int tid = threadIdx.x;
    const int mq  = tid & (NQ - 1);
    const int ch  = tid >> 3;
    const int b     = blockIdx.x;
    const int mbase = blockIdx.y * M_PER_CTA;
    const int m0    = mbase + 4 * mq;

    // Stage anchor widths/heights once. Anchor area is recomputed per iter
    // with one FMUL (fma pipe has headroom) instead of a second LDS.64 --
    // halves per-iter smem traffic (L1% tracks dur_us across R4..R7).
    // Centered boxes => iw = min(aw,gw) bitwise (0.5w exact; clips dead).
    for (int i = tid; i < N_ANCH; i += NTHREADS) {
        sWH[i] = reinterpret_cast<const float2*>(anchors)[i];
    }
    __syncthreads();

    float gw[4], gh[4], aB[4];
    #pragma unroll
    for (int j = 0; j < 4; j++) {
        const float4 g = reinterpret_cast<const float4*>(gt)[b * M_ + m0 + j];
        gw[j] = g.z - g.x;
        gh[j] = g.w - g.y;
        aB[j] = gw[j] * gh[j];
    }
    const u64 aB01 = pk(aB[0], aB[1]);
    const u64 aB23 = pk(aB[2], aB[3]);

    float best[4]  = {-1.0f, -1.0f, -1.0f, -1.0f};
    int   bestn[4] = {0, 0, 0, 0};

    // Indexed stores: unrolled-by-4 body gets compile-time offsets folded
    // into STG [R+imm]; base pointer advances once per 4 iterations.
    ulonglong2* pp = reinterpret_cast<ulonglong2*>(
        ious + (size_t)b * N_ANCH * M_ + (size_t)ch * CH * M_ + m0);

    #pragma unroll 4
    for (int i = 0; i < CH; i++) {
        const float2 a  = sWH[ch * CH + i];
        const float  azs = a.x * a.y;
        const u64    az  = pk(azs, azs);
        const u64 iw01 = pk(fminf(a.x, gw[0]), fminf(a.x, gw[1]));
        const u64 ih01 = pk(fminf(a.y, gh[0]), fminf(a.y, gh[1]));
        const u64 iw23 = pk(fminf(a.x, gw[2]), fminf(a.x, gw[3]));
        const u64 ih23 = pk(fminf(a.y, gh[2]), fminf(a.y, gh[3]));
        const u64 x01  = mul2(iw01, ih01);          // inter
        const u64 x23  = mul2(iw23, ih23);
        const u64 s01  = add2(az, aB01);            // area_a + area_b
        const u64 s23  = add2(az, aB23);
        const u64 q01  = iou_div2(x01, s01);
        const u64 q23  = iou_div2(x23, s23);

        ulonglong2 st; st.x = q01; st.y = q23;
        pp[(size_t)i * (M_ / 4)] = st;

        float r0, r1, r2, r3;
        upk(q01, r0, r1); upk(q23, r2, r3);
        if (r0 > best[0]) { best[0] = r0; bestn[0] = i; }
        if (r1 > best[1]) { best[1] = r1; bestn[1] = i; }
        if (r2 > best[2]) { best[2] = r2; bestn[2] = i; }
        if (r3 > best[3]) { best[3] = r3; bestn[3] = i; }
    }

    #pragma unroll
    for (int j = 0; j < 4; j++) {
        sPm[ch][4 * mq + j] = best[j];
        sPi[ch][4 * mq + j] = ch * CH + bestn[j];
    }
    __syncthreads();

    // Fold chunks ascending, strict-greater: first-occurring max wins,
    // matching jnp.argmax exactly.
    if (tid < M_PER_CTA) {
        float bv = sPm[0][tid];
        int   bi = sPi[0][tid];
        #pragma unroll
        for (int c = 1; c < NCH; c++) {
            const float v = sPm[c][tid];
            if (v > bv) { bv = v; bi = sPi[c][tid]; }
        }
        matches[b * M_ + mbase + tid] = (float)bi;
    }
}

extern "C" void kernel_launch(void* const* d_in, const int* in_sizes, int n_in,
                              void* d_out, int out_size)
{
    const float* anchors = (const float*)d_in[0];
    const float* gt      = (const float*)d_in[1];
    float* out = (float*)d_out;

    const size_t ious_elems = (size_t)B_ * N_ANCH * M_;
    const size_t ious_off   = (size_t)out_size - ious_elems;

    matcher_kernel<<<dim3(B_, M_ / M_PER_CTA), NTHREADS>>>(
        anchors, gt, out, out + ious_off);
}